// round 6
// baseline (speedup 1.0000x reference)
#include <cuda_runtime.h>
#include <cstdint>

#define NB 64
#define NT 256
#define NC 2048
#define NH 512
#define NO 11
#define THRESH 1.0f
#define LEAKV  0.003f
#define OLEAK  0.0015f

// Scratch (static device allocations — allowed)
__device__ float g_Iin[NB * NT * NH];      // [b][t][h] = x @ w1^T
__device__ float g_WrecT[NH * NH];         // [j][h] = w_rec[h][j]

typedef unsigned long long ull;

// Packed fp32x2 FMA: two independent IEEE fp32 fma.rn per instruction (FFMA2).
__device__ __forceinline__ void fma2(ull& d, ull a, ull b) {
    asm("fma.rn.f32x2 %0, %1, %2, %0;" : "+l"(d) : "l"(a), "l"(b));
}
// Duplicate one float into both halves of a 64-bit pair (register-side, no smem cost)
__device__ __forceinline__ ull dup2(float v) {
    ull r;
    asm("mov.b64 %0, {%1, %1};" : "=l"(r) : "f"(v));
    return r;
}

// ---------------------------------------------------------------------------
// Prep: transpose w_rec
// ---------------------------------------------------------------------------
__global__ void prep_kernel(const float* __restrict__ w_rec) {
    int idx = blockIdx.x * blockDim.x + threadIdx.x;
    if (idx < NH * NH) {
        int h = idx / NH, j = idx % NH;
        g_WrecT[j * NH + h] = w_rec[idx];
    }
}

// ---------------------------------------------------------------------------
// fp32 GEMM via packed FFMA2, BIT-EXACT to the R1 SIMT kernel:
// each output element is one fp32 fma.rn chain, k ascending 0..2047.
// Iin[M,N] = x[M,K] @ w1[N,K]^T ; M=16384, N=512, K=2048.
// 128x128 CTA tile, BK=8, 256 threads, 8x8 outputs/thread (8x4 f32x2 pairs).
// A plain in smem (R1 layout, 64 B/thread/k crossbar); {a,a} packed in regs.
// Double-buffered, register prefetch, one __syncthreads per chunk.
// ---------------------------------------------------------------------------
#define BM 128
#define BN 128
#define BKK 8
#define SSTRIDE 132   // floats per k-row (pad 4): 528 B, 16B-aligned

__global__ __launch_bounds__(256) void gemm_kernel(
    const float* __restrict__ A,    // x  [M,K]
    const float* __restrict__ W)    // w1 [N,K]
{
    const int K = NC;
    __shared__ __align__(16) float sA[2][BKK][SSTRIDE];
    __shared__ __align__(16) float sB[2][BKK][SSTRIDE];

    const int tid  = threadIdx.x;
    const int trow = tid / 16;          // 0..15 -> m block of 8
    const int tcol = tid % 16;          // 0..15 -> n block of 8
    const int lrow = tid >> 1;          // 0..127
    const int lcol = (tid & 1) * 4;     // 0 or 4

    const float* Ab = A + (size_t)blockIdx.y * BM * K + (size_t)lrow * K + lcol;
    const float* Wb = W + (size_t)blockIdx.x * BN * K + (size_t)lrow * K + lcol;

    ull acc[8][4];
    #pragma unroll
    for (int m = 0; m < 8; ++m)
        #pragma unroll
        for (int p = 0; p < 4; ++p) acc[m][p] = 0ull;

    float4 av, wv;

    // Prologue: load + stage chunk 0
    av = *(const float4*)(Ab);
    wv = *(const float4*)(Wb);
    sA[0][lcol + 0][lrow] = av.x;
    sA[0][lcol + 1][lrow] = av.y;
    sA[0][lcol + 2][lrow] = av.z;
    sA[0][lcol + 3][lrow] = av.w;
    sB[0][lcol + 0][lrow] = wv.x;
    sB[0][lcol + 1][lrow] = wv.y;
    sB[0][lcol + 2][lrow] = wv.z;
    sB[0][lcol + 3][lrow] = wv.w;
    __syncthreads();

    const int NITER = K / BKK;   // 256
    for (int kc = 0; kc < NITER; ++kc) {
        const int cur = kc & 1;
        const int nxt = cur ^ 1;

        // Register prefetch of next chunk (hides DRAM/L2 latency)
        if (kc + 1 < NITER) {
            av = *(const float4*)(Ab + (kc + 1) * BKK);
            wv = *(const float4*)(Wb + (kc + 1) * BKK);
        }

        // Compute current chunk: k ascending, one FFMA2 per output-pair per k.
        #pragma unroll
        for (int k = 0; k < BKK; ++k) {
            // A: 8 floats (2x LDS.128), duplicated into {a,a} pairs in regs
            float4 a03 = *(const float4*)&sA[cur][k][trow * 8 + 0];
            float4 a47 = *(const float4*)&sA[cur][k][trow * 8 + 4];
            // B: 8 floats (2x LDS.128) naturally form 4 aligned 64-bit pairs
            ulonglong2 b01 = *(const ulonglong2*)&sB[cur][k][tcol * 8 + 0];
            ulonglong2 b23 = *(const ulonglong2*)&sB[cur][k][tcol * 8 + 4];

            ull ad[8];
            ad[0] = dup2(a03.x); ad[1] = dup2(a03.y);
            ad[2] = dup2(a03.z); ad[3] = dup2(a03.w);
            ad[4] = dup2(a47.x); ad[5] = dup2(a47.y);
            ad[6] = dup2(a47.z); ad[7] = dup2(a47.w);
            ull bf[4] = { b01.x, b01.y, b23.x, b23.y };

            #pragma unroll
            for (int m = 0; m < 8; ++m) {
                fma2(acc[m][0], ad[m], bf[0]);
                fma2(acc[m][1], ad[m], bf[1]);
                fma2(acc[m][2], ad[m], bf[2]);
                fma2(acc[m][3], ad[m], bf[3]);
            }
        }

        // Stage next chunk into the other buffer
        if (kc + 1 < NITER) {
            sA[nxt][lcol + 0][lrow] = av.x;
            sA[nxt][lcol + 1][lrow] = av.y;
            sA[nxt][lcol + 2][lrow] = av.z;
            sA[nxt][lcol + 3][lrow] = av.w;
            sB[nxt][lcol + 0][lrow] = wv.x;
            sB[nxt][lcol + 1][lrow] = wv.y;
            sB[nxt][lcol + 2][lrow] = wv.z;
            sB[nxt][lcol + 3][lrow] = wv.w;
            __syncthreads();
        }
    }

    // Epilogue: identical bytes/addresses as R1's float4 stores
    float* Cb = g_Iin + ((size_t)blockIdx.y * BM + trow * 8) * NH
                      + blockIdx.x * BN + tcol * 8;
    #pragma unroll
    for (int m = 0; m < 8; ++m) {
        *(ulonglong2*)(Cb + (size_t)m * NH + 0) = make_ulonglong2(acc[m][0], acc[m][1]);
        *(ulonglong2*)(Cb + (size_t)m * NH + 4) = make_ulonglong2(acc[m][2], acc[m][3]);
    }
}

// ---------------------------------------------------------------------------
// Sequential SNN (unchanged, known-good): one CTA / batch, 1 thread / neuron.
// ---------------------------------------------------------------------------
__global__ __launch_bounds__(512) void snn_kernel(
    const float* __restrict__ w2,   // [O,H]
    float* __restrict__ out)        // [B,O]
{
    const int b    = blockIdx.x;
    const int h    = threadIdx.x;
    const int lane = h & 31;
    const int warp = h >> 5;

    __shared__ int   s_list[NH];
    __shared__ int   s_wcnt[16];
    __shared__ int   s_base[16];
    __shared__ int   s_total;
    __shared__ float s_w2t[NH * 12];

    #pragma unroll
    for (int o = 0; o < NO; ++o)
        s_w2t[h * 12 + o] = w2[o * NH + h];

    float v1 = 0.f, rec = 0.f, v2 = 0.f, osum = 0.f;
    const float* Iin_b = g_Iin + (size_t)b * NT * NH + h;

    __syncthreads();
    float iin = Iin_b[0];

    for (int t = 0; t < NT; ++t) {
        v1 += iin + rec - LEAKV;
        bool spike = (v1 >= THRESH);
        if (spike) v1 -= THRESH;

        unsigned m = __ballot_sync(0xffffffffu, spike);
        if (lane == 0) s_wcnt[warp] = __popc(m);
        __syncthreads();
        if (h == 0) {
            int s = 0;
            #pragma unroll
            for (int w = 0; w < 16; ++w) { s_base[w] = s; s += s_wcnt[w]; }
            s_total = s;
        }
        __syncthreads();
        if (spike)
            s_list[s_base[warp] + __popc(m & ((1u << lane) - 1u))] = h;
        __syncthreads();

        const int total = s_total;
        if (t + 1 < NT) iin = Iin_b[(size_t)(t + 1) * NH];

        rec = 0.f;
        #pragma unroll 4
        for (int i = 0; i < total; ++i)
            rec += g_WrecT[s_list[i] * NH + h];

        if (h < NO) {
            float i2 = 0.f;
            #pragma unroll 4
            for (int i = 0; i < total; ++i)
                i2 += s_w2t[s_list[i] * 12 + h];
            v2 = fmaxf(v2 + i2 - OLEAK, 0.f);
            osum += v2;
        }
        __syncthreads();
    }

    if (h < NO) out[b * NO + h] = osum * (1.0f / (float)NT);
}

// ---------------------------------------------------------------------------
extern "C" void kernel_launch(void* const* d_in, const int* in_sizes, int n_in,
                              void* d_out, int out_size) {
    const float* x     = (const float*)d_in[0];
    const float* w1    = (const float*)d_in[1];
    const float* w_rec = (const float*)d_in[2];
    const float* w2    = (const float*)d_in[3];
    float* out = (float*)d_out;

    prep_kernel<<<(NH * NH + 255) / 256, 256>>>(w_rec);

    dim3 gg(NH / BN, (NB * NT) / BM);   // (4, 128)
    gemm_kernel<<<gg, 256>>>(x, w1);

    snn_kernel<<<NB, NH>>>(w2, out);
}

// round 8
// speedup vs baseline: 1.3164x; 1.3164x over previous
#include <cuda_runtime.h>
#include <cstdint>

#define NB 64
#define NT 256
#define NC 2048
#define NH 512
#define NO 11
#define THRESH 1.0f
#define LEAKV  0.003f
#define OLEAK  0.0015f

// Scratch (static device allocations — allowed)
__device__ float g_Iin[NB * NT * NH];      // [b][t][h] = x @ w1^T
__device__ float g_WrecT[NH * NH];         // [j][h] = w_rec[h][j]
__device__ int   g_doneY[128];             // per-y-tile completion counters (->4)

// ---------------------------------------------------------------------------
// Prep: transpose w_rec + zero flags (runs before fused kernel each replay)
// ---------------------------------------------------------------------------
__global__ void prep_kernel(const float* __restrict__ w_rec) {
    int idx = blockIdx.x * blockDim.x + threadIdx.x;
    if (blockIdx.x == 0 && threadIdx.x < 128) g_doneY[threadIdx.x] = 0;
    if (idx < NH * NH) {
        int h = idx / NH, j = idx % NH;
        g_WrecT[j * NH + h] = w_rec[idx];
    }
}

// ---------------------------------------------------------------------------
// Fused kernel: blocks 0..511 = GEMM tiles, blocks 512..575 = SNN batches.
//
// GEMM: Iin[M,N] = x[M,K] @ w1[N,K]^T, M=16384 N=512 K=2048.
//   128x128 tile, BK=8, 512 threads, 4x8 outputs/thread.
//   BIT-EXACT to R1: each output = one fp32 fmaf chain, k ascending 0..2047.
//   Tile order: even y-tiles first (blocks 0..255), then odd (256..511), so
//   each batch's first half (t<128) is available early.
//   Publishes g_doneY[y] (4 CTAs per y-tile).
//
// SNN: one block per batch, 1 thread/neuron (R1-verbatim arithmetic).
//   Two phases: wait tile 2b -> t=0..127; wait tile 2b+1 -> t=128..255.
// ---------------------------------------------------------------------------
#define BM 128
#define BN 128
#define BKK 8
#define SSTRIDE 132

union SmemU {
    struct {
        float sA[2][BKK][SSTRIDE];
        float sB[2][BKK][SSTRIDE];
    } g;
    struct {
        int   list[NH];
        int   wcnt[16];
        int   base[16];
        int   total;
        float w2t[NH * 12];
    } s;
};

__global__ __launch_bounds__(512) void fused_kernel(
    const float* __restrict__ A,    // x  [M,K]
    const float* __restrict__ W,    // w1 [N,K]
    const float* __restrict__ w2,   // [O,H]
    float* __restrict__ out)        // [B,O]
{
    __shared__ SmemU sm;
    const int blk = blockIdx.x;
    const int tid = threadIdx.x;

    if (blk < 512) {
        // ================= GEMM branch =================
        const int K = NC;
        const int q = (blk < 256) ? (blk >> 2) : ((blk - 256) >> 2);
        const int y = (blk < 256) ? (2 * q) : (2 * q + 1);
        const int x = blk & 3;
        const int M0 = y * BM;
        const int N0 = x * BN;

        // Staging: arow 0..127, acol in {0,2,4,6} -> float2 each for A and B
        const int arow = tid >> 2;
        const int acol = (tid & 3) * 2;
        const float* Ab = A + (size_t)(M0 + arow) * K + acol;
        const float* Wb = W + (size_t)(N0 + arow) * K + acol;

        // Compute mapping: 4 rows x 8 cols per thread
        const int trow = tid >> 4;      // 0..31
        const int tcol = tid & 15;      // 0..15

        float acc[4][8];
        #pragma unroll
        for (int m = 0; m < 4; ++m)
            #pragma unroll
            for (int n = 0; n < 8; ++n) acc[m][n] = 0.f;

        float2 av, wv;

        // Prologue: chunk 0
        av = *(const float2*)(Ab);
        wv = *(const float2*)(Wb);
        sm.g.sA[0][acol + 0][arow] = av.x;
        sm.g.sA[0][acol + 1][arow] = av.y;
        sm.g.sB[0][acol + 0][arow] = wv.x;
        sm.g.sB[0][acol + 1][arow] = wv.y;
        __syncthreads();

        const int NITER = K / BKK;   // 256
        for (int kc = 0; kc < NITER; ++kc) {
            const int cur = kc & 1;
            const int nxt = cur ^ 1;

            if (kc + 1 < NITER) {
                av = *(const float2*)(Ab + (kc + 1) * BKK);
                wv = *(const float2*)(Wb + (kc + 1) * BKK);
            }

            #pragma unroll
            for (int k = 0; k < BKK; ++k) {
                float4 a4 = *(const float4*)&sm.g.sA[cur][k][trow * 4];
                float4 b0 = *(const float4*)&sm.g.sB[cur][k][tcol * 8];
                float4 b1 = *(const float4*)&sm.g.sB[cur][k][tcol * 8 + 4];
                float af[4] = {a4.x, a4.y, a4.z, a4.w};
                float bf[8] = {b0.x, b0.y, b0.z, b0.w, b1.x, b1.y, b1.z, b1.w};
                #pragma unroll
                for (int m = 0; m < 4; ++m)
                    #pragma unroll
                    for (int n = 0; n < 8; ++n)
                        acc[m][n] = fmaf(af[m], bf[n], acc[m][n]);
            }

            if (kc + 1 < NITER) {
                sm.g.sA[nxt][acol + 0][arow] = av.x;
                sm.g.sA[nxt][acol + 1][arow] = av.y;
                sm.g.sB[nxt][acol + 0][arow] = wv.x;
                sm.g.sB[nxt][acol + 1][arow] = wv.y;
                __syncthreads();
            }
        }

        // Epilogue: same bytes/addresses as R1 layout
        float* Cb = g_Iin + ((size_t)M0 + trow * 4) * NH + N0 + tcol * 8;
        #pragma unroll
        for (int m = 0; m < 4; ++m) {
            *(float4*)(Cb + (size_t)m * NH + 0) =
                make_float4(acc[m][0], acc[m][1], acc[m][2], acc[m][3]);
            *(float4*)(Cb + (size_t)m * NH + 4) =
                make_float4(acc[m][4], acc[m][5], acc[m][6], acc[m][7]);
        }

        // Publish tile completion
        __threadfence();
        __syncthreads();
        if (tid == 0) atomicAdd(&g_doneY[y], 1);

    } else {
        // ================= SNN branch =================
        const int b    = blk - 512;
        const int h    = tid;
        const int lane = h & 31;
        const int warp = h >> 5;

        #pragma unroll
        for (int o = 0; o < NO; ++o)
            sm.s.w2t[h * 12 + o] = w2[o * NH + h];
        __syncthreads();

        float v1 = 0.f, rec = 0.f, v2 = 0.f, osum = 0.f;
        const float* Iin_b = g_Iin + (size_t)b * NT * NH + h;

        #pragma unroll 1
        for (int ph = 0; ph < 2; ++ph) {
            // Wait for this half-batch's GEMM tile (4 CTAs)
            if (h == 0) {
                volatile int* flag = &g_doneY[2 * b + ph];
                while (*flag < 4) __nanosleep(256);
                __threadfence();
            }
            __syncthreads();

            const int t0 = ph * 128, t1 = t0 + 128;
            float iin = Iin_b[(size_t)t0 * NH];

            for (int t = t0; t < t1; ++t) {
                v1 += iin + rec - LEAKV;
                bool spike = (v1 >= THRESH);
                if (spike) v1 -= THRESH;

                unsigned m = __ballot_sync(0xffffffffu, spike);
                if (lane == 0) sm.s.wcnt[warp] = __popc(m);
                __syncthreads();
                if (h == 0) {
                    int s = 0;
                    #pragma unroll
                    for (int w = 0; w < 16; ++w) { sm.s.base[w] = s; s += sm.s.wcnt[w]; }
                    sm.s.total = s;
                }
                __syncthreads();
                if (spike)
                    sm.s.list[sm.s.base[warp] + __popc(m & ((1u << lane) - 1u))] = h;
                __syncthreads();

                const int total = sm.s.total;
                if (t + 1 < t1) iin = Iin_b[(size_t)(t + 1) * NH];

                rec = 0.f;
                #pragma unroll 4
                for (int i = 0; i < total; ++i)
                    rec += g_WrecT[sm.s.list[i] * NH + h];

                if (h < NO) {
                    float i2 = 0.f;
                    #pragma unroll 4
                    for (int i = 0; i < total; ++i)
                        i2 += sm.s.w2t[sm.s.list[i] * 12 + h];
                    v2 = fmaxf(v2 + i2 - OLEAK, 0.f);
                    osum += v2;
                }
                __syncthreads();
            }
        }

        if (h < NO) out[b * NO + h] = osum * (1.0f / (float)NT);
    }
}

// ---------------------------------------------------------------------------
extern "C" void kernel_launch(void* const* d_in, const int* in_sizes, int n_in,
                              void* d_out, int out_size) {
    const float* x     = (const float*)d_in[0];
    const float* w1    = (const float*)d_in[1];
    const float* w_rec = (const float*)d_in[2];
    const float* w2    = (const float*)d_in[3];
    float* out = (float*)d_out;

    prep_kernel<<<(NH * NH + 255) / 256, 256>>>(w_rec);
    fused_kernel<<<576, 512>>>(x, w1, w2, out);
}

// round 9
// speedup vs baseline: 1.9385x; 1.4726x over previous
#include <cuda_runtime.h>
#include <cstdint>

#define NB 64
#define NT 256
#define NC 2048
#define NH 512
#define NO 11
#define THRESH 1.0f
#define LEAKV  0.003f
#define OLEAK  0.0015f

// Scratch (static device allocations — allowed)
__device__ float g_Iin[NB * NT * NH];      // [b][t][h] = x @ w1^T
__device__ float g_WrecT[NH * NH];         // [j][h] = w_rec[h][j]
__device__ int   g_doneY[128];             // per-y-tile completion counters (->4)

// ---------------------------------------------------------------------------
// Prep: zero flags + transpose w_rec (runs before fused kernel each replay)
// ---------------------------------------------------------------------------
__global__ void prep_kernel(const float* __restrict__ w_rec) {
    int idx = blockIdx.x * blockDim.x + threadIdx.x;
    if (blockIdx.x == 0 && threadIdx.x < 128) g_doneY[threadIdx.x] = 0;
    if (idx < NH * NH) {
        int h = idx / NH, j = idx % NH;
        g_WrecT[j * NH + h] = w_rec[idx];
    }
}

// ---------------------------------------------------------------------------
// Fused kernel, 512 blocks x 256 threads.
//  All blocks: one 128x128 GEMM tile (R1's exact fp32 mapping -> bit-exact Iin).
//    Tile order: blocks 0..255 -> even y-tiles, 256..511 -> odd y-tiles.
//  Blocks 0..63: after their tile, morph into SNN batch blk (spin on g_doneY).
// ---------------------------------------------------------------------------
#define BM 128
#define BN 128
#define BKK 8
#define SSTRIDE 132

union SmemU {
    struct {
        float sA[2][BKK][SSTRIDE];
        float sB[2][BKK][SSTRIDE];
    } g;
    struct {
        int   list[NH];
        int   wcnt[16];
        int   base[16];
        int   total;
        float w2t[NH * 12];
    } s;
};

__global__ __launch_bounds__(256) void fused_kernel(
    const float* __restrict__ A,    // x  [M,K]
    const float* __restrict__ W,    // w1 [N,K]
    const float* __restrict__ w2,   // [O,H]
    float* __restrict__ out)        // [B,O]
{
    __shared__ SmemU sm;
    const int blk = blockIdx.x;
    const int tid = threadIdx.x;

    // ===================== GEMM phase (all 512 blocks) =====================
    {
        const int K = NC;
        // even y-tiles first, then odd
        const int y = (blk < 256) ? ((blk >> 2) * 2) : (((blk - 256) >> 2) * 2 + 1);
        const int x = blk & 3;
        const int M0 = y * BM;
        const int N0 = x * BN;

        const int trow = tid / 16;          // 0..15
        const int tcol = tid % 16;          // 0..15
        const int lrow = tid >> 1;          // 0..127
        const int lcol = (tid & 1) * 4;     // 0 or 4

        const float* Ab = A + (size_t)M0 * K + (size_t)lrow * K + lcol;
        const float* Wb = W + (size_t)N0 * K + (size_t)lrow * K + lcol;

        float acc[8][8];
        #pragma unroll
        for (int m = 0; m < 8; ++m)
            #pragma unroll
            for (int n = 0; n < 8; ++n) acc[m][n] = 0.f;

        float af[8], bf[8];
        float4 av, wv;

        // Prologue: chunk 0
        av = *(const float4*)(Ab);
        wv = *(const float4*)(Wb);
        sm.g.sA[0][lcol + 0][lrow] = av.x;
        sm.g.sA[0][lcol + 1][lrow] = av.y;
        sm.g.sA[0][lcol + 2][lrow] = av.z;
        sm.g.sA[0][lcol + 3][lrow] = av.w;
        sm.g.sB[0][lcol + 0][lrow] = wv.x;
        sm.g.sB[0][lcol + 1][lrow] = wv.y;
        sm.g.sB[0][lcol + 2][lrow] = wv.z;
        sm.g.sB[0][lcol + 3][lrow] = wv.w;
        __syncthreads();

        const int NITER = K / BKK;   // 256
        for (int kc = 0; kc < NITER; ++kc) {
            const int cur = kc & 1;
            const int nxt = cur ^ 1;

            if (kc + 1 < NITER) {
                av = *(const float4*)(Ab + (kc + 1) * BKK);
                wv = *(const float4*)(Wb + (kc + 1) * BKK);
            }

            #pragma unroll
            for (int k = 0; k < BKK; ++k) {
                #pragma unroll
                for (int m = 0; m < 8; m += 4) {
                    float4 t = *(const float4*)&sm.g.sA[cur][k][trow * 8 + m];
                    af[m] = t.x; af[m + 1] = t.y; af[m + 2] = t.z; af[m + 3] = t.w;
                }
                #pragma unroll
                for (int n = 0; n < 8; n += 4) {
                    float4 t = *(const float4*)&sm.g.sB[cur][k][tcol * 8 + n];
                    bf[n] = t.x; bf[n + 1] = t.y; bf[n + 2] = t.z; bf[n + 3] = t.w;
                }
                #pragma unroll
                for (int m = 0; m < 8; ++m)
                    #pragma unroll
                    for (int n = 0; n < 8; ++n)
                        acc[m][n] = fmaf(af[m], bf[n], acc[m][n]);
            }

            if (kc + 1 < NITER) {
                sm.g.sA[nxt][lcol + 0][lrow] = av.x;
                sm.g.sA[nxt][lcol + 1][lrow] = av.y;
                sm.g.sA[nxt][lcol + 2][lrow] = av.z;
                sm.g.sA[nxt][lcol + 3][lrow] = av.w;
                sm.g.sB[nxt][lcol + 0][lrow] = wv.x;
                sm.g.sB[nxt][lcol + 1][lrow] = wv.y;
                sm.g.sB[nxt][lcol + 2][lrow] = wv.z;
                sm.g.sB[nxt][lcol + 3][lrow] = wv.w;
                __syncthreads();
            }
        }

        // Epilogue (R1 bytes/addresses)
        float* Cb = g_Iin + ((size_t)M0 + trow * 8) * NH + N0 + tcol * 8;
        #pragma unroll
        for (int m = 0; m < 8; ++m) {
            #pragma unroll
            for (int n = 0; n < 8; n += 4) {
                *(float4*)(Cb + (size_t)m * NH + n) =
                    make_float4(acc[m][n], acc[m][n + 1], acc[m][n + 2], acc[m][n + 3]);
            }
        }

        // Publish tile completion
        __threadfence();
        __syncthreads();
        if (tid == 0) atomicAdd(&g_doneY[y], 1);
    }

    if (blk >= NB) return;

    // ===================== SNN phase (blocks 0..63) =====================
    __syncthreads();   // smem reuse barrier (GEMM buffers -> SNN layout)

    const int b    = blk;
    const int h    = tid;            // neuron pair (h, h+256)
    const int lane = tid & 31;
    const int warp = tid >> 5;       // 0..7

    #pragma unroll
    for (int o = 0; o < NO; ++o) {
        sm.s.w2t[h * 12 + o]          = w2[o * NH + h];
        sm.s.w2t[(h + 256) * 12 + o]  = w2[o * NH + h + 256];
    }
    __syncthreads();

    float v1a = 0.f, v1b = 0.f, recA = 0.f, recB = 0.f;
    float v2 = 0.f, osum = 0.f;
    const float* Iin_b = g_Iin + (size_t)b * NT * NH;

    #pragma unroll 1
    for (int ph = 0; ph < 2; ++ph) {
        // Wait for this half-batch's GEMM y-tile (4 CTAs)
        if (tid == 0) {
            volatile int* flag = &g_doneY[2 * b + ph];
            while (*flag < 4) __nanosleep(128);
            __threadfence();
        }
        __syncthreads();

        const int t0 = ph * 128, t1 = t0 + 128;
        float iinA = Iin_b[(size_t)t0 * NH + h];
        float iinB = Iin_b[(size_t)t0 * NH + h + 256];

        for (int t = t0; t < t1; ++t) {
            // LIF updates for both neurons (same math/order as R1)
            v1a += iinA + recA - LEAKV;
            bool spkA = (v1a >= THRESH);
            if (spkA) v1a -= THRESH;
            v1b += iinB + recB - LEAKV;
            bool spkB = (v1b >= THRESH);
            if (spkB) v1b -= THRESH;

            unsigned mA = __ballot_sync(0xffffffffu, spkA);
            unsigned mB = __ballot_sync(0xffffffffu, spkB);
            if (lane == 0) {
                sm.s.wcnt[warp]     = __popc(mA);
                sm.s.wcnt[8 + warp] = __popc(mB);
            }
            __syncthreads();
            if (tid == 0) {
                int s = 0;
                #pragma unroll
                for (int w = 0; w < 16; ++w) { sm.s.base[w] = s; s += sm.s.wcnt[w]; }
                sm.s.total = s;
            }
            __syncthreads();
            // list content/order identical to R1: h ascending 0..511
            unsigned lm = (1u << lane) - 1u;
            if (spkA) sm.s.list[sm.s.base[warp]     + __popc(mA & lm)] = h;
            if (spkB) sm.s.list[sm.s.base[8 + warp] + __popc(mB & lm)] = h + 256;
            __syncthreads();

            const int total = sm.s.total;
            if (t + 1 < t1) {
                iinA = Iin_b[(size_t)(t + 1) * NH + h];
                iinB = Iin_b[(size_t)(t + 1) * NH + h + 256];
            }

            recA = 0.f; recB = 0.f;
            #pragma unroll 4
            for (int i = 0; i < total; ++i) {
                const float* row = g_WrecT + (size_t)sm.s.list[i] * NH;
                recA += row[h];
                recB += row[h + 256];
            }

            if (h < NO) {
                float i2 = 0.f;
                #pragma unroll 4
                for (int i = 0; i < total; ++i)
                    i2 += sm.s.w2t[sm.s.list[i] * 12 + h];
                v2 = fmaxf(v2 + i2 - OLEAK, 0.f);
                osum += v2;
            }
            __syncthreads();
        }
    }

    if (h < NO) out[b * NO + h] = osum * (1.0f / (float)NT);
}

// ---------------------------------------------------------------------------
extern "C" void kernel_launch(void* const* d_in, const int* in_sizes, int n_in,
                              void* d_out, int out_size) {
    const float* x     = (const float*)d_in[0];
    const float* w1    = (const float*)d_in[1];
    const float* w_rec = (const float*)d_in[2];
    const float* w2    = (const float*)d_in[3];
    float* out = (float*)d_out;

    prep_kernel<<<(NH * NH + 255) / 256, 256>>>(w_rec);
    fused_kernel<<<512, 256>>>(x, w1, w2, out);
}